// round 8
// baseline (speedup 1.0000x reference)
#include <cuda_runtime.h>
#include <math.h>
#include <float.h>

#define NODES 10242
#define NROWS 40968          // BATCH*NODES
#define NG    16380
#define LATN  91
#define LONN  180
#define CH    64
#define BATCH 4

// 2D bins: lon-major so each (lonbin, z-range) scan is ONE contiguous run
#define ZB    64
#define LB    32
#define NBIN2 (ZB*LB)
#define ZW    (2.0f/ZB)
#define LONW  (6.28318530717958647f/LB)
#define TCUT  0.02f          // prune bar on chord^2 (8-NN radius^2, huge margin)
#define DZW   0.14142136f    // sqrt(TCUT)
#define PIF   3.14159274f
#define TWOPI 6.28318530717958647f

#define LPB   8              // lons per knn block (angle-adjacent)
#define NSLOT ((LONN + LPB - 1) / LPB)   // 23
#define CAP   2048           // staged-candidate buffer (40KB smem)

// Scratch (no cudaMalloc allowed)
__device__ int    g_binCnt[NBIN2];
__device__ int    g_binStart[NBIN2 + 1];
__device__ int    g_binCur[NBIN2];
__device__ float4 g_sorted[NODES];      // {x,y,z,m2} bin-sorted
__device__ int    g_sidx[NODES];        // original index
__device__ int    g_lonOrder[LONN];     // angle-rank -> original lon index
__device__ float  g_WT[CH * CH];        // g_WT[c*64+c'] = W[c'][c]
__device__ float  g_MW[NROWS * CH];     // M @ W^T  (10.5 MB, L2-resident)
__device__ float  g_knw[NG * 8];
__device__ int    g_kni[NG * 8];

__device__ __forceinline__ int zbin(float z) {
    int b = (int)((z + 1.0f) * (ZB * 0.5f));
    return min(max(b, 0), ZB - 1);
}
__device__ __forceinline__ int lonbin(float phi) {
    int b = (int)(phi * (1.0f / LONW));
    return min(max(b, 0), LB - 1);
}
__device__ __forceinline__ bool lex_less(float a, int ai, float b, int bi) {
    return (a < b) || (a == b && ai < bi);
}

// ---------------------------------------------------------------------------
// Zero bin counters + transpose W. grid 8 x 256.
// ---------------------------------------------------------------------------
__global__ void zero_tw_kernel(const float* __restrict__ W) {
    int i = blockIdx.x * 256 + threadIdx.x;          // 0..2047
    g_binCnt[i] = 0;
#pragma unroll
    for (int k = 0; k < 2; ++k) {
        int e = i * 2 + k;                           // 0..4095
        g_WT[(e & 63) * 64 + (e >> 6)] = W[e];
    }
}

// ---------------------------------------------------------------------------
__global__ void hist_kernel(const float* __restrict__ mv) {
    int i = blockIdx.x * 256 + threadIdx.x;
    if (i < NODES) {
        float x = mv[3*i], y = mv[3*i+1], z = mv[3*i+2];
        float phi = atan2f(y, x);
        if (phi < 0.f) phi += TWOPI;
        atomicAdd(&g_binCnt[lonbin(phi) * ZB + zbin(z)], 1);
    }
}

// ---------------------------------------------------------------------------
// Exclusive scan of 2048 bin counts + rank-sort of the 180 lon angles.
// One block of 256 threads.
// ---------------------------------------------------------------------------
__global__ __launch_bounds__(256) void scan_sort_kernel(const float* __restrict__ lon) {
    __shared__ int ps[256];
    const int t = threadIdx.x;
    int loc[8]; int s = 0;
#pragma unroll
    for (int k = 0; k < 8; ++k) { loc[k] = g_binCnt[t * 8 + k]; s += loc[k]; }
    ps[t] = s;
    __syncthreads();
    for (int off = 1; off < 256; off <<= 1) {
        int v = (t >= off) ? ps[t - off] : 0;
        __syncthreads();
        ps[t] += v;
        __syncthreads();
    }
    int run = ps[t] - s;                             // exclusive prefix
#pragma unroll
    for (int k = 0; k < 8; ++k) {
        g_binStart[t * 8 + k] = run;
        g_binCur[t * 8 + k]   = run;
        run += loc[k];
    }
    if (t == 255) g_binStart[NBIN2] = run;

    // rank-sort lons (stable on (value, index))
    if (t < LONN) {
        float vi = lon[t];
        int rank = 0;
        for (int j = 0; j < LONN; ++j) {
            float vj = lon[j];
            rank += (vj < vi) || (vj == vi && j < t);
        }
        g_lonOrder[rank] = t;
    }
}

// Scatter into bin order; pack {x,y,z,m2} with the reference's exact rounding.
__global__ void scatter_kernel(const float* __restrict__ mv) {
    int i = blockIdx.x * 256 + threadIdx.x;
    if (i < NODES) {
        float x = mv[3*i], y = mv[3*i+1], z = mv[3*i+2];
        float phi = atan2f(y, x);
        if (phi < 0.f) phi += TWOPI;
        float m2 = __fadd_rn(__fadd_rn(__fmul_rn(x,x), __fmul_rn(y,y)), __fmul_rn(z,z));
        int pos = atomicAdd(&g_binCur[lonbin(phi) * ZB + zbin(z)], 1);
        g_sorted[pos] = make_float4(x, y, z, m2);
        g_sidx[pos]   = i;
    }
}

// ---------------------------------------------------------------------------
// GEMM: g_MW[r][c'] = sum_c M[r][c] * W[c'][c]. Block = 32 rows, 256 threads.
// ---------------------------------------------------------------------------
__global__ __launch_bounds__(256) void gemm_kernel(const float* __restrict__ M) {
    __shared__ float s_A[32 * 65];
    const int tid = threadIdx.x;
    const int r0  = blockIdx.x * 32;

    for (int i = tid; i < 32 * 64; i += 256) {
        int r = i >> 6, c = i & 63;
        int row = min(r0 + r, NROWS - 1);
        s_A[r * 65 + c] = M[(size_t)row * 64 + c];
    }
    __syncthreads();

    const int r  = tid >> 3;
    const int cg = tid & 7;
    float acc[8];
#pragma unroll
    for (int j = 0; j < 8; ++j) acc[j] = 0.f;

    const float* ar = &s_A[r * 65];
#pragma unroll 8
    for (int cc = 0; cc < 64; ++cc) {
        float a = ar[cc];
        float4 w0 = *(const float4*)&g_WT[cc * 64 + cg * 8];
        float4 w1 = *(const float4*)&g_WT[cc * 64 + cg * 8 + 4];
        acc[0] = __fmaf_rn(a, w0.x, acc[0]); acc[1] = __fmaf_rn(a, w0.y, acc[1]);
        acc[2] = __fmaf_rn(a, w0.z, acc[2]); acc[3] = __fmaf_rn(a, w0.w, acc[3]);
        acc[4] = __fmaf_rn(a, w1.x, acc[4]); acc[5] = __fmaf_rn(a, w1.y, acc[5]);
        acc[6] = __fmaf_rn(a, w1.z, acc[6]); acc[7] = __fmaf_rn(a, w1.w, acc[7]);
    }
    int row = r0 + r;
    if (row < NROWS) {
        float* op = &g_MW[(size_t)row * 64 + cg * 8];
        ((float4*)op)[0] = make_float4(acc[0], acc[1], acc[2], acc[3]);
        ((float4*)op)[1] = make_float4(acc[4], acc[5], acc[6], acc[7]);
    }
}

// ---------------------------------------------------------------------------
// KNN: block = (lat row, 8 ANGLE-ADJACENT lons), one warp per grid point.
// The block's union window (z-band x [lo0-dphi, lo7+dphi]) is staged into
// smem with 256-thread coalesced bursts (high MLP, no per-warp latency
// chains); each warp scans the flat list. Exact reference-rounded d2 +
// lex (d2, idx) stable insert -> selected set identical to the full scan.
// ---------------------------------------------------------------------------
__global__ __launch_bounds__(256) void knn_kernel(const float* __restrict__ lat,
                                                  const float* __restrict__ lon) {
    __shared__ float4 s_c[CAP];
    __shared__ int    s_ci[CAP];
    __shared__ int    s_segS[LB], s_segL[LB];

    const int tid  = threadIdx.x;
    const int lane = tid & 31;
    const int wid  = tid >> 5;
    const int row  = blockIdx.x / NSLOT;
    const int slot = blockIdx.x % NSLOT;
    const int posw = slot * LPB + wid;
    const bool valid = posw < LONN;
    const int pos  = min(posw, LONN - 1);
    const int li   = g_lonOrder[pos];

    const float la = lat[row];
    const float lo = lon[li];
    const float cl = cosf(la);
    const float x  = __fmul_rn(cl, cosf(lo));
    const float y  = __fmul_rn(cl, sinf(lo));
    const float z  = sinf(la);
    const float g2 = __fadd_rn(__fadd_rn(__fmul_rn(x,x), __fmul_rn(y,y)), __fmul_rn(z,z));

    // ---- block-uniform window (z identical across warps; dphi from z only)
    const float z0  = z;
    const int   zlo = zbin(z0 - DZW);
    const int   zhi = zbin(z0 + DZW);

    const float rq   = fabsf(cl);
    const float zext = fminf(1.0f, fabsf(z0) + DZW + ZW);
    const float rn2  = 1.0f - zext * zext;
    const float rnm  = rn2 > 0.f ? sqrtf(rn2) : 0.f;
    const float den  = 2.0f * rq * rnm;
    float dphi;
    if (den < 1e-6f) dphi = PIF;
    else {
        float ca = 1.0f - TCUT / den;
        dphi = (ca <= -1.0f) ? PIF : acosf(fminf(ca, 1.0f));
    }
    dphi += 1e-3f;

    const float lo0 = lon[g_lonOrder[slot * LPB]];
    const float lo7 = lon[g_lonOrder[min(slot * LPB + LPB - 1, LONN - 1)]];
    int lb_lo = (int)floorf((lo0 - dphi) * (1.0f / LONW));
    int lb_hi = (int)floorf((lo7 + dphi) * (1.0f / LONW));
    int nb = lb_hi - lb_lo + 1;
    if (nb > LB) { nb = LB; lb_lo = 0; }

    if (tid < nb) {
        int lb = (lb_lo + tid) & (LB - 1);
        int s  = g_binStart[lb * ZB + zlo];
        int e  = g_binStart[lb * ZB + zhi + 1];
        s_segS[tid] = s; s_segL[tid] = e - s;
    }
    __syncthreads();

    float dd[8]; int xi[8];
#pragma unroll
    for (int j = 0; j < 8; ++j) { dd[j] = TCUT; xi[j] = 0x7fffffff; }

    // ---- staged scan (uniform control flow; per-thread copies of shared state)
    int seg = 0, segOff = 0;
    while (seg < nb) {
        int fill = 0;
        while (seg < nb && fill < CAP) {
            int start = s_segS[seg], len = s_segL[seg];
            int take  = min(len - segOff, CAP - fill);
            for (int i = tid; i < take; i += 256) {
                s_c[fill + i]  = g_sorted[start + segOff + i];
                s_ci[fill + i] = g_sidx[start + segOff + i];
            }
            fill += take; segOff += take;
            if (segOff >= len) { ++seg; segOff = 0; }
        }
        __syncthreads();
        for (int j = lane; j < fill; j += 32) {
            float4 p = s_c[j];
            float d2 = __fsub_rn(__fadd_rn(g2, p.w),
                       __fmul_rn(2.0f, __fmaf_rn(z, p.z,
                                       __fmaf_rn(y, p.y,
                                       __fmul_rn(x, p.x)))));
            int vi = s_ci[j];
            if (d2 < dd[7] || (d2 == dd[7] && vi < xi[7])) {   // rare
                float v = d2;
#pragma unroll
                for (int c8 = 0; c8 < 8; ++c8) {
                    bool sw = lex_less(v, vi, dd[c8], xi[c8]);
                    float nv = sw ? dd[c8] : v;
                    int   ni = sw ? xi[c8] : vi;
                    dd[c8] = sw ? v  : dd[c8];
                    xi[c8] = sw ? vi : xi[c8];
                    v = nv; vi = ni;
                }
            }
        }
        __syncthreads();
    }

    // ---- warp-merge: 8 rounds of lex argmin over lane heads (stable top-8)
    float myd = 0.f; int myi = 0;
#pragma unroll
    for (int r = 0; r < 8; ++r) {
        float bv = dd[0]; int bi = xi[0]; int bl = lane;
#pragma unroll
        for (int off = 16; off > 0; off >>= 1) {
            float ov = __shfl_down_sync(0xffffffffu, bv, off);
            int   oi = __shfl_down_sync(0xffffffffu, bi, off);
            int   ol = __shfl_down_sync(0xffffffffu, bl, off);
            if (lex_less(ov, oi, bv, bi)) { bv = ov; bi = oi; bl = ol; }
        }
        bv = __shfl_sync(0xffffffffu, bv, 0);
        bi = __shfl_sync(0xffffffffu, bi, 0);
        bl = __shfl_sync(0xffffffffu, bl, 0);
        if (lane == bl) {
#pragma unroll
            for (int j = 0; j < 7; ++j) { dd[j] = dd[j+1]; xi[j] = xi[j+1]; }
            dd[7] = FLT_MAX; xi[7] = 0x7fffffff;
        }
        if (lane == r) { myd = bv; myi = bi; }
    }

    // ---- softmax over -dist among the 8 (lanes 0..7); rank0 = nearest
    float dist = sqrtf(fmaxf(myd, 1e-12f));
    float dmn  = __shfl_sync(0xffffffffu, dist, 0);
    float ww = 0.f;
    if (lane < 8) ww = expf(__fsub_rn(dmn, dist));
    float ssum = ww;
#pragma unroll
    for (int off = 16; off > 0; off >>= 1) ssum += __shfl_xor_sync(0xffffffffu, ssum, off);
    const int g = row * LONN + li;
    if (valid && lane < 8) {
        g_knw[g * 8 + lane] = __fdiv_rn(ww, ssum);
        g_kni[g * 8 + lane] = myi;
    }
}

// ---------------------------------------------------------------------------
// Gather: out[b][c'][g] = bias[c'] + sum_k w_k * MW[b][idx_k][c'].
// Block = 8 consecutive g, 256 threads = (b, c'). Coalesced float4 stores.
// ---------------------------------------------------------------------------
__global__ __launch_bounds__(256) void gather_kernel(const float* __restrict__ bias,
                                                     float* __restrict__ out) {
    __shared__ float s_w[8][8];
    __shared__ int   s_i[8][8];

    const int tid = threadIdx.x;
    const int g0  = blockIdx.x * 8;

    if (tid < 64) {
        int gg = tid >> 3, k = tid & 7;
        int g = g0 + gg;
        if (g < NG) { s_w[gg][k] = g_knw[g * 8 + k]; s_i[gg][k] = g_kni[g * 8 + k]; }
        else        { s_w[gg][k] = 0.f;              s_i[gg][k] = 0; }
    }
    __syncthreads();

    const int b = tid >> 6;
    const int c = tid & 63;
    const float bv = bias[c];
    const float* Mb = g_MW + (size_t)b * NODES * CH + c;

    float r[8];
#pragma unroll
    for (int gg = 0; gg < 8; ++gg) {
        float a = bv;
#pragma unroll
        for (int k = 0; k < 8; ++k)
            a = __fmaf_rn(s_w[gg][k], Mb[(size_t)s_i[gg][k] * CH], a);
        r[gg] = a;
    }

    float* op = out + (size_t)(b * CH + c) * NG + g0;
    if (g0 + 8 <= NG) {
        ((float4*)op)[0] = make_float4(r[0], r[1], r[2], r[3]);
        ((float4*)op)[1] = make_float4(r[4], r[5], r[6], r[7]);
    } else {
#pragma unroll
        for (int gg = 0; gg < 8; ++gg)
            if (g0 + gg < NG) op[gg] = r[gg];
    }
}

// ---------------------------------------------------------------------------
extern "C" void kernel_launch(void* const* d_in, const int* in_sizes, int n_in,
                              void* d_out, int out_size) {
    const float* mesh_output   = (const float*)d_in[0];  // (4,10242,64)
    const float* mesh_vertices = (const float*)d_in[1];  // (10242,3)
    const float* lat           = (const float*)d_in[2];  // (91,)
    const float* lon           = (const float*)d_in[3];  // (180,)
    const float* W             = (const float*)d_in[4];  // (64,64)
    const float* bvec          = (const float*)d_in[5];  // (64,)
    float* out = (float*)d_out;                          // (4,64,91,180)

    zero_tw_kernel<<<NBIN2 / 256, 256>>>(W);
    hist_kernel<<<(NODES + 255) / 256, 256>>>(mesh_vertices);
    scan_sort_kernel<<<1, 256>>>(lon);
    scatter_kernel<<<(NODES + 255) / 256, 256>>>(mesh_vertices);
    gemm_kernel<<<(NROWS + 31) / 32, 256>>>(mesh_output);
    knn_kernel<<<LATN * NSLOT, 256>>>(lat, lon);
    gather_kernel<<<(NG + 7) / 8, 256>>>(bvec, out);
}

// round 9
// speedup vs baseline: 1.2010x; 1.2010x over previous
#include <cuda_runtime.h>
#include <math.h>
#include <float.h>

#define NODES 10242
#define NROWS 40968          // BATCH*NODES
#define NG    16380
#define LATN  91
#define LONN  180
#define CH    64
#define BATCH 4

// 2D bins: lon-major so each (lonbin, z-range) scan is ONE contiguous run
#define ZB    64
#define LB    32
#define NBIN2 (ZB*LB)
#define ZW    (2.0f/ZB)
#define LONW  (6.28318530717958647f/LB)
#define TCUT  0.02f          // prune bar on chord^2 (8-NN radius^2, huge margin)
#define DZW   0.14142136f    // sqrt(TCUT)
#define PIF   3.14159274f
#define TWOPI 6.28318530717958647f

#define K1_GRID 321          // all-resident (<= 148 SMs * 6 blocks @33KB smem)
#define GT    64             // gemm tile rows
#define NTILE ((NROWS + GT - 1) / GT)   // 641

// Scratch (no cudaMalloc allowed)
__device__ int    g_ctrl[NBIN2 + 2];    // [0:2048)=hist counts; [2048],[2049]=barriers (memset per call)
__device__ int    g_binStart[NBIN2 + 1];
__device__ int    g_binCur[NBIN2];
__device__ float4 g_sorted[NODES];      // {x,y,z,m2} bin-sorted
__device__ int    g_sidx[NODES];        // original index
__device__ float  g_MW[NROWS * CH];     // M @ W^T  (10.5 MB, L2-resident)

__device__ __forceinline__ int zbin(float z) {
    int b = (int)((z + 1.0f) * (ZB * 0.5f));
    return min(max(b, 0), ZB - 1);
}
__device__ __forceinline__ int lonbin(float phi) {
    int b = (int)(phi * (1.0f / LONW));
    return min(max(b, 0), LB - 1);
}
__device__ __forceinline__ bool lex_less(float a, int ai, float b, int bi) {
    return (a < b) || (a == b && ai < bi);
}

// Grid-wide barrier: all K1_GRID blocks are simultaneously resident (smem/reg
// footprint checked), so spin-wait is deadlock-free. Counters zeroed by the
// memset node before each launch.
__device__ __forceinline__ void grid_sync(int idx) {
    __syncthreads();
    if (threadIdx.x == 0) {
        __threadfence();
        atomicAdd(&g_ctrl[NBIN2 + idx], 1);
        while (atomicAdd(&g_ctrl[NBIN2 + idx], 0) < (int)gridDim.x) __nanosleep(64);
    }
    __syncthreads();
}

// ---------------------------------------------------------------------------
// K1: fused  hist -> sync -> scan(block 0) -> sync -> scatter -> gemm.
// gemm: g_MW[r][c'] = sum_c M[r][c]*W[c'][c]; W transposed into smem (LDS,
// no LSU floor), 2 rows/thread, tiles strided across blocks.
// ---------------------------------------------------------------------------
__global__ __launch_bounds__(256) void prep_gemm_kernel(const float* __restrict__ mv,
                                                        const float* __restrict__ W,
                                                        const float* __restrict__ M) {
    __shared__ float s_A[GT * 65];
    __shared__ float s_WT[64 * 64];     // s_WT[c*64+c'] = W[c'][c]
    __shared__ int   s_ps[256];
    const int tid = threadIdx.x;
    const int bid = blockIdx.x;

    // W transpose into smem (needed only for gemm phase; no cross-block dep)
#pragma unroll
    for (int k = 0; k < 16; ++k) {
        int e = tid + k * 256;                       // 0..4095
        s_WT[(e & 63) * 64 + (e >> 6)] = W[e];
    }

    // ---- phase A: histogram (<=1 node per thread at this grid size)
    {
        int i = bid * 256 + tid;
        if (i < NODES) {
            float x = mv[3*i], y = mv[3*i+1], z = mv[3*i+2];
            float phi = atan2f(y, x);
            if (phi < 0.f) phi += TWOPI;
            atomicAdd(&g_ctrl[lonbin(phi) * ZB + zbin(z)], 1);
        }
    }
    grid_sync(0);

    // ---- phase B: exclusive scan of 2048 bins on block 0
    if (bid == 0) {
        int loc[8]; int s = 0;
#pragma unroll
        for (int k = 0; k < 8; ++k) { loc[k] = g_ctrl[tid * 8 + k]; s += loc[k]; }
        s_ps[tid] = s;
        __syncthreads();
        for (int off = 1; off < 256; off <<= 1) {
            int v = (tid >= off) ? s_ps[tid - off] : 0;
            __syncthreads();
            s_ps[tid] += v;
            __syncthreads();
        }
        int run = s_ps[tid] - s;
#pragma unroll
        for (int k = 0; k < 8; ++k) {
            g_binStart[tid * 8 + k] = run;
            g_binCur[tid * 8 + k]   = run;
            run += loc[k];
        }
        if (tid == 255) g_binStart[NBIN2] = run;
    }
    grid_sync(1);

    // ---- phase C: scatter (atomic cursors; downstream selection is
    //      lex-stable on (d2, idx) so in-bin order doesn't matter)
    {
        int i = bid * 256 + tid;
        if (i < NODES) {
            float x = mv[3*i], y = mv[3*i+1], z = mv[3*i+2];
            float phi = atan2f(y, x);
            if (phi < 0.f) phi += TWOPI;
            float m2 = __fadd_rn(__fadd_rn(__fmul_rn(x,x), __fmul_rn(y,y)), __fmul_rn(z,z));
            int pos = atomicAdd(&g_binCur[lonbin(phi) * ZB + zbin(z)], 1);
            g_sorted[pos] = make_float4(x, y, z, m2);
            g_sidx[pos]   = i;
        }
    }

    // ---- phase D: gemm (no cross-block dependency with scatter)
    for (int t = bid; t < NTILE; t += K1_GRID) {
        __syncthreads();                             // protect s_A reuse
        for (int i = tid; i < GT * 64; i += 256) {
            int rr = i >> 6, c = i & 63;
            int row = min(t * GT + rr, NROWS - 1);
            s_A[rr * 65 + c] = M[(size_t)row * 64 + c];
        }
        __syncthreads();

        const int r  = tid >> 3;        // 0..31 -> rows r, r+32
        const int cg = tid & 7;         // c' group of 8
        float a0[8], a1[8];
#pragma unroll
        for (int j = 0; j < 8; ++j) { a0[j] = 0.f; a1[j] = 0.f; }

        const float* ar0 = &s_A[r * 65];
        const float* ar1 = &s_A[(r + 32) * 65];
#pragma unroll 8
        for (int cc = 0; cc < 64; ++cc) {
            float x0 = ar0[cc];                      // 4-way broadcast LDS
            float x1 = ar1[cc];
            float4 w0 = *(const float4*)&s_WT[cc * 64 + cg * 8];
            float4 w1 = *(const float4*)&s_WT[cc * 64 + cg * 8 + 4];
            a0[0] = __fmaf_rn(x0, w0.x, a0[0]); a0[1] = __fmaf_rn(x0, w0.y, a0[1]);
            a0[2] = __fmaf_rn(x0, w0.z, a0[2]); a0[3] = __fmaf_rn(x0, w0.w, a0[3]);
            a0[4] = __fmaf_rn(x0, w1.x, a0[4]); a0[5] = __fmaf_rn(x0, w1.y, a0[5]);
            a0[6] = __fmaf_rn(x0, w1.z, a0[6]); a0[7] = __fmaf_rn(x0, w1.w, a0[7]);
            a1[0] = __fmaf_rn(x1, w0.x, a1[0]); a1[1] = __fmaf_rn(x1, w0.y, a1[1]);
            a1[2] = __fmaf_rn(x1, w0.z, a1[2]); a1[3] = __fmaf_rn(x1, w0.w, a1[3]);
            a1[4] = __fmaf_rn(x1, w1.x, a1[4]); a1[5] = __fmaf_rn(x1, w1.y, a1[5]);
            a1[6] = __fmaf_rn(x1, w1.z, a1[6]); a1[7] = __fmaf_rn(x1, w1.w, a1[7]);
        }
        int row0 = t * GT + r;
        int row1 = row0 + 32;
        if (row0 < NROWS) {
            float* op = &g_MW[(size_t)row0 * 64 + cg * 8];
            ((float4*)op)[0] = make_float4(a0[0], a0[1], a0[2], a0[3]);
            ((float4*)op)[1] = make_float4(a0[4], a0[5], a0[6], a0[7]);
        }
        if (row1 < NROWS) {
            float* op = &g_MW[(size_t)row1 * 64 + cg * 8];
            ((float4*)op)[0] = make_float4(a1[0], a1[1], a1[2], a1[3]);
            ((float4*)op)[1] = make_float4(a1[4], a1[5], a1[6], a1[7]);
        }
    }
}

// ---------------------------------------------------------------------------
// K2: fused KNN + gather (verbatim R7 logic — passed with rel_err 2.08e-6).
// Block = 8 consecutive grid points, warp per point.
// ---------------------------------------------------------------------------
__global__ __launch_bounds__(256) void knn_gather_kernel(const float* __restrict__ lat,
                                                         const float* __restrict__ lon,
                                                         const float* __restrict__ bias,
                                                         float* __restrict__ out) {
    __shared__ float s_w[8][8];
    __shared__ int   s_i[8][8];

    const int tid  = threadIdx.x;
    const int lane = tid & 31;
    const int wid  = tid >> 5;
    const int g0   = blockIdx.x * 8;
    const int gw   = min(g0 + wid, NG - 1);          // clamp (store guarded)
    const int row  = gw / LONN;
    const int li   = gw - row * LONN;

    // ---- Phase A: KNN ----
    {
        const float la = lat[row];
        const float lo = lon[li];
        const float cl = cosf(la);
        const float x  = __fmul_rn(cl, cosf(lo));
        const float y  = __fmul_rn(cl, sinf(lo));
        const float z  = sinf(la);
        const float g2 = __fadd_rn(__fadd_rn(__fmul_rn(x,x), __fmul_rn(y,y)), __fmul_rn(z,z));

        float dd[8]; int xi[8];
#pragma unroll
        for (int j = 0; j < 8; ++j) { dd[j] = TCUT; xi[j] = 0x7fffffff; }

        const int zlo = zbin(z - DZW);
        const int zhi = zbin(z + DZW);

        const float rq   = fabsf(cl);
        const float zext = fminf(1.0f, fabsf(z) + DZW + ZW);
        const float rn2  = 1.0f - zext * zext;
        const float rnm  = rn2 > 0.f ? sqrtf(rn2) : 0.f;
        const float den  = 2.0f * rq * rnm;
        float dphi;
        if (den < 1e-6f) dphi = PIF;
        else {
            float ca = 1.0f - TCUT / den;
            dphi = (ca <= -1.0f) ? PIF : acosf(fminf(ca, 1.0f));
        }
        dphi += 1e-3f;
        int lb_lo = (int)floorf((lo - dphi) * (1.0f / LONW));
        int lb_hi = (int)floorf((lo + dphi) * (1.0f / LONW));
        int nb = lb_hi - lb_lo + 1;
        if (nb > LB) { nb = LB; lb_lo = 0; }

        for (int tt = 0; tt < nb; ++tt) {
            const int lb = (lb_lo + tt) & (LB - 1);
            const int s  = g_binStart[lb * ZB + zlo];
            const int e  = g_binStart[lb * ZB + zhi + 1];
            for (int j = s + lane; j < e; j += 32) {
                float4 p = g_sorted[j];
                float d2 = __fsub_rn(__fadd_rn(g2, p.w),
                           __fmul_rn(2.0f, __fmaf_rn(z, p.z,
                                           __fmaf_rn(y, p.y,
                                           __fmul_rn(x, p.x)))));
                int vi = g_sidx[j];
                if (d2 < dd[7] || (d2 == dd[7] && vi < xi[7])) {   // rare
                    float v = d2;
#pragma unroll
                    for (int c8 = 0; c8 < 8; ++c8) {
                        bool sw = lex_less(v, vi, dd[c8], xi[c8]);
                        float nv = sw ? dd[c8] : v;
                        int   ni = sw ? xi[c8] : vi;
                        dd[c8] = sw ? v  : dd[c8];
                        xi[c8] = sw ? vi : xi[c8];
                        v = nv; vi = ni;
                    }
                }
            }
        }

        // warp-merge: 8 rounds of lex argmin over lane heads (stable top-8)
        float myd = 0.f; int myi = 0;
#pragma unroll
        for (int r = 0; r < 8; ++r) {
            float bv = dd[0]; int bi = xi[0]; int bl = lane;
#pragma unroll
            for (int off = 16; off > 0; off >>= 1) {
                float ov = __shfl_down_sync(0xffffffffu, bv, off);
                int   oi = __shfl_down_sync(0xffffffffu, bi, off);
                int   ol = __shfl_down_sync(0xffffffffu, bl, off);
                if (lex_less(ov, oi, bv, bi)) { bv = ov; bi = oi; bl = ol; }
            }
            bv = __shfl_sync(0xffffffffu, bv, 0);
            bi = __shfl_sync(0xffffffffu, bi, 0);
            bl = __shfl_sync(0xffffffffu, bl, 0);
            if (lane == bl) {
#pragma unroll
                for (int j = 0; j < 7; ++j) { dd[j] = dd[j+1]; xi[j] = xi[j+1]; }
                dd[7] = FLT_MAX; xi[7] = 0x7fffffff;
            }
            if (lane == r) { myd = bv; myi = bi; }
        }

        float dist = sqrtf(fmaxf(myd, 1e-12f));
        float dmn  = __shfl_sync(0xffffffffu, dist, 0);
        float ww = 0.f;
        if (lane < 8) ww = expf(__fsub_rn(dmn, dist));
        float ssum = ww;
#pragma unroll
        for (int off = 16; off > 0; off >>= 1) ssum += __shfl_xor_sync(0xffffffffu, ssum, off);
        if (lane < 8) {
            s_w[wid][lane] = __fdiv_rn(ww, ssum);
            s_i[wid][lane] = myi;
        }
    }
    __syncthreads();

    // ---- Phase B: gather + bias ----
    const int b = tid >> 6;
    const int c = tid & 63;
    const float bv = bias[c];
    const float* Mb = g_MW + (size_t)b * NODES * CH + c;

    float r[8];
#pragma unroll
    for (int gg = 0; gg < 8; ++gg) {
        float a = bv;
#pragma unroll
        for (int k = 0; k < 8; ++k)
            a = __fmaf_rn(s_w[gg][k], Mb[(size_t)s_i[gg][k] * CH], a);
        r[gg] = a;
    }

    float* op = out + (size_t)(b * CH + c) * NG + g0;
    if (g0 + 8 <= NG) {
        ((float4*)op)[0] = make_float4(r[0], r[1], r[2], r[3]);
        ((float4*)op)[1] = make_float4(r[4], r[5], r[6], r[7]);
    } else {
#pragma unroll
        for (int gg = 0; gg < 8; ++gg)
            if (g0 + gg < NG) op[gg] = r[gg];
    }
}

// ---------------------------------------------------------------------------
extern "C" void kernel_launch(void* const* d_in, const int* in_sizes, int n_in,
                              void* d_out, int out_size) {
    const float* mesh_output   = (const float*)d_in[0];  // (4,10242,64)
    const float* mesh_vertices = (const float*)d_in[1];  // (10242,3)
    const float* lat           = (const float*)d_in[2];  // (91,)
    const float* lon           = (const float*)d_in[3];  // (180,)
    const float* W             = (const float*)d_in[4];  // (64,64)
    const float* bvec          = (const float*)d_in[5];  // (64,)
    float* out = (float*)d_out;                          // (4,64,91,180)

    // zero hist counters + grid-barrier counters (graph memset node)
    void* cp = nullptr;
    cudaGetSymbolAddress(&cp, g_ctrl);
    cudaMemsetAsync(cp, 0, sizeof(int) * (NBIN2 + 2), 0);

    prep_gemm_kernel<<<K1_GRID, 256>>>(mesh_vertices, W, mesh_output);
    knn_gather_kernel<<<(NG + 7) / 8, 256>>>(lat, lon, bvec, out);
}